// round 16
// baseline (speedup 1.0000x reference)
#include <cuda_runtime.h>
#include <cuda_bf16.h>
#include <math.h>
#include <stdint.h>

#define Bn     4
#define Cin    512
#define Tn     4
#define HW     961
#define THW    3844
#define CCn    256
#define CPn    42
#define CP3    126
#define AGGIN  1016
#define NLOC   61504
#define NQT    61
#define VROW   968
#define NPAD   3848

typedef unsigned long long u64;
typedef unsigned int u32;

// ---------------- f32x2 packed-math helpers ----------------
__device__ __forceinline__ u64 pack2(float lo, float hi) {
    u64 r; asm("mov.b64 %0, {%1,%2};" : "=l"(r) : "f"(lo), "f"(hi)); return r;
}
__device__ __forceinline__ u64 dup2(float v) { return pack2(v, v); }
__device__ __forceinline__ void unpack2(u64 p, float& lo, float& hi) {
    asm("mov.b64 {%0,%1}, %2;" : "=f"(lo), "=f"(hi) : "l"(p));
}
__device__ __forceinline__ u64 fma2(u64 a, u64 b, u64 c) {
    u64 d; asm("fma.rn.f32x2 %0, %1, %2, %3;" : "=l"(d) : "l"(a), "l"(b), "l"(c)); return d;
}
__device__ __forceinline__ u64 mul2(u64 a, u64 b) {
    u64 d; asm("mul.rn.f32x2 %0, %1, %2;" : "=l"(d) : "l"(a), "l"(b)); return d;
}

// ---------------- bf16 mma helpers ----------------
__device__ __forceinline__ u32 pkbf(float lo, float hi) {
    u32 d; asm("cvt.rn.bf16x2.f32 %0, %1, %2;" : "=r"(d) : "f"(hi), "f"(lo)); return d;
}
__device__ __forceinline__ void mma_bf16(float* d, u32 a0, u32 a1, u32 a2, u32 a3,
                                         u32 b0, u32 b1)
{
    asm("mma.sync.aligned.m16n8k16.row.col.f32.bf16.bf16.f32 "
        "{%0,%1,%2,%3},{%4,%5,%6,%7},{%8,%9},{%0,%1,%2,%3};"
        : "+f"(d[0]), "+f"(d[1]), "+f"(d[2]), "+f"(d[3])
        : "r"(a0), "r"(a1), "r"(a2), "r"(a3), "r"(b0), "r"(b1));
}
__device__ __forceinline__ void ldsm4(u32& r0, u32& r1, u32& r2, u32& r3, u32 addr) {
    asm volatile("ldmatrix.sync.aligned.m8n8.x4.shared.b16 {%0,%1,%2,%3}, [%4];"
                 : "=r"(r0), "=r"(r1), "=r"(r2), "=r"(r3) : "r"(addr));
}
__device__ __forceinline__ void ldsm4t(u32& r0, u32& r1, u32& r2, u32& r3, u32 addr) {
    asm volatile("ldmatrix.sync.aligned.m8n8.x4.trans.shared.b16 {%0,%1,%2,%3}, [%4];"
                 : "=r"(r0), "=r"(r1), "=r"(r2), "=r"(r3) : "r"(addr));
}
__device__ __forceinline__ void cpa16(u32 smem_addr, const void* gptr) {
    asm volatile("cp.async.cg.shared.global [%0], [%1], 16;"
                 :: "r"(smem_addr), "l"(gptr));
}
#define CP_COMMIT() asm volatile("cp.async.commit_group;")
#define CP_WAIT(N)  asm volatile("cp.async.wait_group %0;" :: "n"(N))

__device__ __forceinline__ void bfsplit(float v, __nv_bfloat16& h, __nv_bfloat16& l) {
    h = __float2bfloat16(v);
    l = __float2bfloat16(v - __bfloat162float(h));
}

// ---------------- scratch ----------------
__device__ float d_xp [(size_t)Bn*Cin*THW];
__device__ float d_qmv[(size_t)Bn*768*THW];
__device__ float d_Vt [(size_t)Bn*THW*CCn];
__device__ __align__(16) __nv_bfloat16 d_Qb[(size_t)Bn*THW*CCn + 2048*CCn];
__device__ __align__(16) __nv_bfloat16 d_Mb[(size_t)Bn*THW*CCn + 2048*CCn];
__device__ __align__(16) __nv_bfloat16 d_Vb[(size_t)Bn*CCn*4*VROW + 64];
__device__ __align__(16) __nv_bfloat16 d_xph[(size_t)Bn*512*NPAD + 256];
__device__ __align__(16) __nv_bfloat16 d_xpl[(size_t)Bn*512*NPAD + 256];
__device__ __align__(16) __nv_bfloat16 d_Yh [(size_t)Bn*1024*NPAD + 256];
__device__ __align__(16) __nv_bfloat16 d_Yl [(size_t)Bn*1024*NPAD + 256];
__device__ __align__(16) __nv_bfloat16 d_Wqmvh[3*256*512], d_Wqmvl[3*256*512];
__device__ __align__(16) __nv_bfloat16 d_Waggh[512*1024],  d_Waggl[512*1024];
__device__ float d_R  [(size_t)Bn*Tn*THW*CCn];
__device__ float d_Wt [256*168];
__device__ float d_Craw[(size_t)CP3*NLOC];
__device__ float d_Z  [(size_t)Bn*Cin*THW];
__device__ float d_cmean[CP3], d_crstd[CP3];
__device__ float d_zmean[Cin], d_zrstd[Cin];

// ---------------- split-bf16 GEMM (3-term), 128x128 tile, K-slice 32 ----------------
#define GA_BUF 10240
#define GB_BUF 8704
#define OFF_AH 0
#define OFF_AL 20480
#define OFF_BH 40960
#define OFF_BL 58368
#define GEMM_SMEM 75776

__device__ __forceinline__ void gemm_bfs(const __nv_bfloat16* __restrict__ Ahg,
                                         const __nv_bfloat16* __restrict__ Alg,
                                         const __nv_bfloat16* __restrict__ Bhg,
                                         const __nv_bfloat16* __restrict__ Blg,
                                         float* __restrict__ C,
                                         int M, int N, int K,
                                         int lda, int ldb, int ldc)
{
    extern __shared__ __align__(16) char gsm[];
    const int tid = threadIdx.x;
    const int lane = tid & 31, w = tid >> 5;
    const int g = lane >> 2, q4 = lane & 3;
    const int wm = w & 3, wn = w >> 2;
    const int m0 = blockIdx.y * 128, n0 = blockIdx.x * 128;
    const u32 sb = (u32)__cvta_generic_to_shared(gsm);

    float acc[2][8][4];
#pragma unroll
    for (int mi = 0; mi < 2; mi++)
#pragma unroll
        for (int n = 0; n < 8; n++)
#pragma unroll
            for (int i = 0; i < 4; i++) acc[mi][n][i] = 0.f;

    const int rowA = lane & 15;
    const u32 hiA = (lane & 16) ? 16 : 0;
    const u32 bOffLane = (u32)((lane & 15) * 272 + ((lane >> 4) & 1) * 16);

    const int ns = K / 32;

    {
#pragma unroll
        for (int i = 0; i < 2; i++) {
            int idx = tid + i * 256;
            int ar = idx >> 2, ac = idx & 3;
            size_t ga = (size_t)(m0 + ar) * lda + ac * 8;
            u32 da = ar * 80 + ac * 16;
            cpa16(sb + OFF_AH + da, Ahg + ga);
            cpa16(sb + OFF_AL + da, Alg + ga);
            int kr = idx >> 4, nc = idx & 15;
            size_t gb = (size_t)kr * ldb + n0 + nc * 8;
            u32 db = kr * 272 + nc * 16;
            cpa16(sb + OFF_BH + db, Bhg + gb);
            cpa16(sb + OFF_BL + db, Blg + gb);
        }
        CP_COMMIT();
    }

    for (int s = 0; s < ns; s++) {
        if (s + 1 < ns) {
            int k0 = (s + 1) * 32, bi = (s + 1) & 1;
#pragma unroll
            for (int i = 0; i < 2; i++) {
                int idx = tid + i * 256;
                int ar = idx >> 2, ac = idx & 3;
                size_t ga = (size_t)(m0 + ar) * lda + k0 + ac * 8;
                u32 da = bi * GA_BUF + ar * 80 + ac * 16;
                cpa16(sb + OFF_AH + da, Ahg + ga);
                cpa16(sb + OFF_AL + da, Alg + ga);
                int kr = idx >> 4, nc = idx & 15;
                size_t gb = (size_t)(k0 + kr) * ldb + n0 + nc * 8;
                u32 db = bi * GB_BUF + kr * 272 + nc * 16;
                cpa16(sb + OFF_BH + db, Bhg + gb);
                cpa16(sb + OFF_BL + db, Blg + gb);
            }
            CP_COMMIT();
            CP_WAIT(1);
        } else {
            CP_WAIT(0);
        }
        __syncthreads();

        const int bi = s & 1;
        const u32 aAh = sb + OFF_AH + bi * GA_BUF + (wm * 32 + rowA) * 80 + hiA;
        const u32 aAl = sb + OFF_AL + bi * GA_BUF + (wm * 32 + rowA) * 80 + hiA;
        const u32 bBh = sb + OFF_BH + bi * GB_BUF + bOffLane + wn * 128;
        const u32 bBl = sb + OFF_BL + bi * GB_BUF + bOffLane + wn * 128;

#pragma unroll
        for (int kg = 0; kg < 2; kg++) {
            const u32 akg = kg * 32;
            const u32 bkg = kg * 4352;
            u32 ah[2][4], al[2][4];
            ldsm4(ah[0][0], ah[0][1], ah[0][2], ah[0][3], aAh + akg);
            ldsm4(ah[1][0], ah[1][1], ah[1][2], ah[1][3], aAh + akg + 16 * 80);
            ldsm4(al[0][0], al[0][1], al[0][2], al[0][3], aAl + akg);
            ldsm4(al[1][0], al[1][1], al[1][2], al[1][3], aAl + akg + 16 * 80);

#pragma unroll
            for (int nn = 0; nn < 4; nn++) {
                u32 bh0, bh1, bh2, bh3, bl0, bl1, bl2, bl3;
                ldsm4t(bh0, bh1, bh2, bh3, bBh + bkg + nn * 32);
                ldsm4t(bl0, bl1, bl2, bl3, bBl + bkg + nn * 32);
#pragma unroll
                for (int mi = 0; mi < 2; mi++) {
                    mma_bf16(acc[mi][nn * 2],     ah[mi][0], ah[mi][1], ah[mi][2], ah[mi][3], bh0, bh1);
                    mma_bf16(acc[mi][nn * 2],     ah[mi][0], ah[mi][1], ah[mi][2], ah[mi][3], bl0, bl1);
                    mma_bf16(acc[mi][nn * 2],     al[mi][0], al[mi][1], al[mi][2], al[mi][3], bh0, bh1);
                    mma_bf16(acc[mi][nn * 2 + 1], ah[mi][0], ah[mi][1], ah[mi][2], ah[mi][3], bh2, bh3);
                    mma_bf16(acc[mi][nn * 2 + 1], ah[mi][0], ah[mi][1], ah[mi][2], ah[mi][3], bl2, bl3);
                    mma_bf16(acc[mi][nn * 2 + 1], al[mi][0], al[mi][1], al[mi][2], al[mi][3], bh2, bh3);
                }
            }
        }
        __syncthreads();
    }

#pragma unroll
    for (int mi = 0; mi < 2; mi++) {
        int gm0 = m0 + wm * 32 + mi * 16 + g;
#pragma unroll
        for (int n = 0; n < 8; n++) {
            int gn = n0 + wn * 64 + n * 8 + q4 * 2;
            if (gn < N) {
                float2 t0 = make_float2(acc[mi][n][0], acc[mi][n][1]);
                float2 t1 = make_float2(acc[mi][n][2], acc[mi][n][3]);
                *(float2*)&C[(size_t)gm0 * ldc + gn] = t0;
                *(float2*)&C[(size_t)(gm0 + 8) * ldc + gn] = t1;
            }
        }
    }
}

// ---------------- elementwise / prep ----------------
__global__ void __launch_bounds__(256) k_pool(const float* __restrict__ x)
{
    int idx = blockIdx.x * 256 + threadIdx.x;
    if (idx >= Bn * Cin * Tn * HW) return;
    int p = idx % HW; int rest = idx / HW;
    int h = p / 31, w = p % 31;
    const float* src = x + (size_t)rest * 3969 + (2 * h) * 63 + (2 * w);
    float v = src[0];
    v = fmaxf(v, src[1]);   v = fmaxf(v, src[2]);
    v = fmaxf(v, src[63]);  v = fmaxf(v, src[64]);  v = fmaxf(v, src[65]);
    v = fmaxf(v, src[126]); v = fmaxf(v, src[127]); v = fmaxf(v, src[128]);
    d_xp[idx] = v;
    int t = rest & 3;
    size_t bc = (size_t)(rest >> 2);
    size_t off = bc * NPAD + t * HW + p;
    __nv_bfloat16 hh, ll; bfsplit(v, hh, ll);
    d_xph[off] = hh; d_xpl[off] = ll;
}

__global__ void __launch_bounds__(256) k_wconv_qmv(const float* __restrict__ Wq,
                                                   const float* __restrict__ Wm,
                                                   const float* __restrict__ Wv)
{
    int idx = blockIdx.x * 256 + threadIdx.x;
    if (idx >= 3 * 256 * 512) return;
    int s = idx / (256 * 512), r = idx % (256 * 512);
    const float* W = (s == 0) ? Wq : (s == 1) ? Wm : Wv;
    __nv_bfloat16 hh, ll; bfsplit(W[r], hh, ll);
    d_Wqmvh[idx] = hh; d_Wqmvl[idx] = ll;
}
__global__ void __launch_bounds__(256) k_wconv_agg(const float* __restrict__ Wagg)
{
    int idx = blockIdx.x * 256 + threadIdx.x;
    if (idx >= 512 * 1016) return;
    int m = idx / 1016, k = idx % 1016;
    __nv_bfloat16 hh, ll; bfsplit(Wagg[idx], hh, ll);
    d_Waggh[m * 1024 + k] = hh; d_Waggl[m * 1024 + k] = ll;
}

__global__ void __launch_bounds__(256, 2) k_gemm_qmv()
{
    int z = blockIdx.z; int b = z / 3, s = z % 3;
    gemm_bfs(d_Wqmvh + (size_t)s * 256 * 512, d_Wqmvl + (size_t)s * 256 * 512,
             d_xph + (size_t)b * 512 * NPAD, d_xpl + (size_t)b * 512 * NPAD,
             d_qmv + (size_t)b * 768 * THW + (size_t)s * 256 * THW,
             256, THW, 512, 512, NPAD, THW);
}

__global__ void __launch_bounds__(256, 2) k_gemm_agg()
{
    int b = blockIdx.z;
    gemm_bfs(d_Waggh, d_Waggl,
             d_Yh + (size_t)b * 1024 * NPAD, d_Yl + (size_t)b * 1024 * NPAD,
             d_Z + (size_t)b * Cin * THW,
             Cin, THW, 1024, 1024, NPAD, THW);
}

// transpose Q/M -> bf16 [token][c] (Q pre-scaled 1/16); V -> f32 [j][c] + bf16 [c][mfr][j]
__global__ void __launch_bounds__(256) k_qvt()
{
    __shared__ float t[32][33];
    int z = blockIdx.z; int b = z / 3, s = z % 3;
    const float* src = d_qmv + ((size_t)b * 768 + s * 256) * THW;
    int q0 = blockIdx.x * 32, c0 = blockIdx.y * 32;
    int tx = threadIdx.x & 31, ty = threadIdx.x >> 5;
#pragma unroll
    for (int i = 0; i < 4; i++) {
        int c = c0 + ty + i * 8;
        int q = q0 + tx;
        t[ty + i * 8][tx] = (q < THW) ? src[(size_t)c * THW + q] : 0.f;
    }
    __syncthreads();
    if (s == 2) {
        int q = q0 + tx;
        if (q < THW) {
            int mfr = q / HW, j = q - mfr * HW;
#pragma unroll
            for (int i = 0; i < 4; i++) {
                int c = c0 + ty + i * 8;
                d_Vb[((size_t)(b * 256 + c) * 4 + mfr) * VROW + j] =
                    __float2bfloat16(t[ty + i * 8][tx]);
            }
        }
    }
#pragma unroll
    for (int i = 0; i < 4; i++) {
        int q = q0 + ty + i * 8;
        int c = c0 + tx;
        if (q >= THW) continue;
        float v = t[tx][ty + i * 8];
        size_t off = ((size_t)b * THW + q) * CCn + c;
        if      (s == 0) d_Qb[off] = __float2bfloat16(v * 0.0625f);
        else if (s == 1) d_Mb[off] = __float2bfloat16(v);
        else             d_Vt[off] = v;
    }
}

// ---------------- bf16 flash attention (round-14 scheduling, fused phase C) ----------------
#define AT_QS  0
#define AT_MS  8448
#define AT_PS  16896
#define AT_VS  19200
#define AT_SFM 28416
#define AT_SFS 28544
#define AT_SMEM_BYTES (28672 * 4)

__global__ void __launch_bounds__(256, 2) k_attn()
{
    extern __shared__ __align__(16) u32 smu[];
    u32* Ps = smu + AT_PS;
    float* SfM = (float*)(smu + AT_SFM);
    float* SfS = (float*)(smu + AT_SFS);

    const int b = blockIdx.z, mfr = blockIdx.y;
    const int q0 = blockIdx.x * 64;
    const int tid = threadIdx.x;
    const int w = tid >> 5, lane = tid & 31;
    const int g = lane >> 2, q4 = lane & 3;
    const int qg = w & 3, jh = w >> 2;
    const int qb = qg * 16;

    const __nv_bfloat16* Qg = d_Qb + ((size_t)b * THW + q0) * CCn;
    const __nv_bfloat16* Mg = d_Mb + ((size_t)b * THW + (size_t)mfr * HW) * CCn;
    const __nv_bfloat16* VgBase = d_Vb + ((size_t)b * CCn * 4 + mfr) * VROW;

    const u32 sbase = (u32)__cvta_generic_to_shared(smu);
    const u32 qsB = sbase + AT_QS * 4;
    const u32 msB = sbase + AT_MS * 4;
    const u32 vsB = sbase + AT_VS * 4;

    {
#pragma unroll
        for (int p = 0; p < 8; p++) {
            int e = tid + p * 256;
            int r = e >> 5, seg = e & 31;
            cpa16(qsB + r * 528 + seg * 16, Qg + (size_t)r * CCn + seg * 8);
        }
        CP_COMMIT();
#pragma unroll
        for (int p = 0; p < 8; p++) {
            int e = tid + p * 256;
            int r = e >> 5, seg = e & 31;
            cpa16(msB + r * 528 + seg * 16, Mg + (size_t)r * CCn + seg * 8);
        }
        CP_COMMIT();
    }

    const int rowA = lane & 15;
    const int hiKA = (lane & 16) ? 4 : 0;
    const int rowB = (lane & 7) + ((lane & 16) ? 8 : 0);
    const int hiKB = (lane & 8) ? 4 : 0;
    const u32 aQ  = sbase + (AT_QS + (qb + rowA) * 132 + hiKA) * 4;
    const u32 aM0 = sbase + (AT_MS + (jh * 32 + rowB) * 132 + hiKB) * 4;
    const u32 aM1 = aM0 + 16 * 132 * 4;
    const u32 aP  = sbase + (AT_PS + (qb + rowA) * 36 + hiKA) * 4;
    u32 aV[4];
#pragma unroll
    for (int pp = 0; pp < 4; pp++)
        aV[pp] = sbase + (AT_VS + (jh * 64 + pp * 16 + rowB) * 36 + hiKB) * 4;

    float o[2][8][4];
#pragma unroll
    for (int v = 0; v < 2; v++)
#pragma unroll
        for (int n = 0; n < 8; n++)
#pragma unroll
            for (int i = 0; i < 4; i++) o[v][n][i] = 0.f;
    float rmax0 = -1e30f, rmax1 = -1e30f, rsum0 = 0.f, rsum1 = 0.f;

    for (int j0 = 0; j0 < HW; j0 += 64) {
        CP_WAIT(0);
        __syncthreads();        // M ready; Ps/Vs reuse ordered by this barrier

        // ---- phase A ----
        float s[4][4];
#pragma unroll
        for (int n = 0; n < 4; n++)
#pragma unroll
            for (int i = 0; i < 4; i++) s[n][i] = 0.f;
#pragma unroll
        for (int ks = 0; ks < 16; ks++) {
            u32 a0, a1, a2, a3, b0, b1, b2, b3, c0, c1, c2, c3;
            ldsm4(a0, a1, a2, a3, aQ + ks * 32);
            ldsm4(b0, b1, b2, b3, aM0 + ks * 32);
            ldsm4(c0, c1, c2, c3, aM1 + ks * 32);
            mma_bf16(s[0], a0, a1, a2, a3, b0, b1);
            mma_bf16(s[1], a0, a1, a2, a3, b2, b3);
            mma_bf16(s[2], a0, a1, a2, a3, c0, c1);
            mma_bf16(s[3], a0, a1, a2, a3, c2, c3);
        }

        // ---- softmax: max ----
        float mx0 = -1e30f, mx1 = -1e30f;
#pragma unroll
        for (int n = 0; n < 4; n++) {
            int cb = j0 + jh * 32 + n * 8 + q4 * 2;
            if (cb     >= HW) { s[n][0] = -1e30f; s[n][2] = -1e30f; }
            if (cb + 1 >= HW) { s[n][1] = -1e30f; s[n][3] = -1e30f; }
            mx0 = fmaxf(mx0, fmaxf(s[n][0], s[n][1]));
            mx1 = fmaxf(mx1, fmaxf(s[n][2], s[n][3]));
        }
        mx0 = fmaxf(mx0, __shfl_xor_sync(0xffffffffu, mx0, 1));
        mx0 = fmaxf(mx0, __shfl_xor_sync(0xffffffffu, mx0, 2));
        mx1 = fmaxf(mx1, __shfl_xor_sync(0xffffffffu, mx1, 1));
        mx1 = fmaxf(mx1, __shfl_xor_sync(0xffffffffu, mx1, 2));
        if (q4 == 0) {
            SfM[jh * 64 + qb + g]     = mx0;
            SfM[jh * 64 + qb + g + 8] = mx1;
        }
        __syncthreads();        // phase A done everywhere (Ms free)

        // ---- prefetch next M chunk ----
        {
            const __nv_bfloat16* Mg2 = Mg + (size_t)(j0 + 64) * CCn;
#pragma unroll
            for (int p = 0; p < 8; p++) {
                int e = tid + p * 256;
                int r = e >> 5, seg = e & 31;
                cpa16(msB + r * 528 + seg * 16, Mg2 + (size_t)r * CCn + seg * 8);
            }
            CP_COMMIT();
        }

        // ---- softmax: exp/sum, write P ----
        float nm0 = fmaxf(rmax0, fmaxf(SfM[qb + g],     SfM[64 + qb + g]));
        float nm1 = fmaxf(rmax1, fmaxf(SfM[qb + g + 8], SfM[64 + qb + g + 8]));
        float es0 = __expf(rmax0 - nm0), es1 = __expf(rmax1 - nm1);
        rmax0 = nm0; rmax1 = nm1;
        float sm0 = 0.f, sm1 = 0.f;
#pragma unroll
        for (int n = 0; n < 4; n++) {
            int col = jh * 32 + n * 8 + q4 * 2;
            float p0 = __expf(s[n][0] - nm0), p1 = __expf(s[n][1] - nm0);
            float p2 = __expf(s[n][2] - nm1), p3 = __expf(s[n][3] - nm1);
            sm0 += p0 + p1; sm1 += p2 + p3;
            Ps[(qb + g) * 36 + (col >> 1)]     = pkbf(p0, p1);
            Ps[(qb + g + 8) * 36 + (col >> 1)] = pkbf(p2, p3);
        }
        sm0 += __shfl_xor_sync(0xffffffffu, sm0, 1);
        sm0 += __shfl_xor_sync(0xffffffffu, sm0, 2);
        sm1 += __shfl_xor_sync(0xffffffffu, sm1, 1);
        sm1 += __shfl_xor_sync(0xffffffffu, sm1, 2);
        if (q4 == 0) {
            SfS[jh * 64 + qb + g]     = sm0;
            SfS[jh * 64 + qb + g + 8] = sm1;
        }
        __syncthreads();        // Ps + SfS visible
        float cs0 = SfS[qb + g]     + SfS[64 + qb + g];
        float cs1 = SfS[qb + g + 8] + SfS[64 + qb + g + 8];
        rsum0 = rsum0 * es0 + cs0;
        rsum1 = rsum1 * es1 + cs1;
#pragma unroll
        for (int v = 0; v < 2; v++)
#pragma unroll
            for (int n = 0; n < 8; n++) {
                o[v][n][0] *= es0; o[v][n][1] *= es0;
                o[v][n][2] *= es1; o[v][n][3] *= es1;
            }

        // ---- issue both V chunk copies (round-14 placement) ----
#pragma unroll
        for (int v = 0; v < 2; v++) {
#pragma unroll
            for (int p = 0; p < 4; p++) {
                int e = tid + p * 256;
                int cr = e >> 3, seg = e & 7;
                cpa16(vsB + v * 18432 + cr * 144 + seg * 16,
                      VgBase + ((size_t)(v * 128 + cr) * 4) * VROW + j0 + seg * 8);
            }
            CP_COMMIT();
        }

        // ---- fused phase C: P fragments loaded once, feed both V c-chunks ----
        CP_WAIT(0);             // all queued groups done (M-next was issued earliest)
        __syncthreads();
#pragma unroll
        for (int ks = 0; ks < 4; ks++) {
            u32 pa0, pa1, pa2, pa3;
            ldsm4(pa0, pa1, pa2, pa3, aP + ks * 32);
#pragma unroll
            for (int pp = 0; pp < 4; pp++) {
                u32 vb0, vb1, vb2, vb3;
                ldsm4(vb0, vb1, vb2, vb3, aV[pp] + ks * 32);
                mma_bf16(o[0][pp * 2],     pa0, pa1, pa2, pa3, vb0, vb1);
                mma_bf16(o[0][pp * 2 + 1], pa0, pa1, pa2, pa3, vb2, vb3);
                u32 wb0, wb1, wb2, wb3;
                ldsm4(wb0, wb1, wb2, wb3, aV[pp] + 18432 + ks * 32);
                mma_bf16(o[1][pp * 2],     pa0, pa1, pa2, pa3, wb0, wb1);
                mma_bf16(o[1][pp * 2 + 1], pa0, pa1, pa2, pa3, wb2, wb3);
            }
        }
        // no end sync: next top sync orders Ps/Vs reuse
    }
    CP_WAIT(0);

    float inv0 = 1.f / rsum0, inv1 = 1.f / rsum1;
    int r0 = q0 + qb + g, r1 = r0 + 8;
    float* Rp = d_R + ((size_t)(b * 4 + mfr) * THW) * CCn;
#pragma unroll
    for (int v = 0; v < 2; v++)
#pragma unroll
        for (int n = 0; n < 8; n++) {
            int c = v * 128 + jh * 64 + n * 8 + q4 * 2;
            if (r0 < THW) {
                float2 t0 = make_float2(o[v][n][0] * inv0, o[v][n][1] * inv0);
                *(float2*)&Rp[(size_t)r0 * CCn + c] = t0;
            }
            if (r1 < THW) {
                float2 t1 = make_float2(o[v][n][2] * inv1, o[v][n][3] * inv1);
                *(float2*)&Rp[(size_t)r1 * CCn + c] = t1;
            }
        }
}

__global__ void __launch_bounds__(256) k_wtprep(const float* __restrict__ Wcat,
                                                const float* __restrict__ Wsub,
                                                const float* __restrict__ Wmul)
{
    int idx = blockIdx.x * 256 + threadIdx.x;
    if (idx >= 256 * 168) return;
    int wi = idx % 168, k = idx / 168;
    float v;
    if      (wi < 42)  v = Wcat[wi * 512 + k];
    else if (wi < 84)  v = Wcat[(wi - 42) * 512 + 256 + k];
    else if (wi < 126) v = Wsub[(wi - 84) * 256 + k];
    else               v = Wmul[(wi - 126) * 256 + k];
    d_Wt[idx] = v;
}

// compare: 16 locs/block static smem + LDS.128 row reads
__global__ void __launch_bounds__(128) k_compare()
{
    __shared__ __align__(16) float Rs[256][16];
    __shared__ __align__(16) float Vsm[256][16];
    int loc0 = blockIdx.x * 16;
    int tid = threadIdx.x;
    for (int i = tid; i < 256 * 16; i += 128) {
        int c = i & 255, l = i >> 8;
        int loc = loc0 + l;
        int p = loc % HW; int bs = loc / HW;
        int s = bs & 15, b = bs >> 4;
        int tm = s >> 2, tq = s & 3;
        Rs[c][l]  = d_R [((size_t)((b * 4 + tm) * THW) + tq * HW + p) * CCn + c];
        Vsm[c][l] = d_Vt[((size_t)b * THW + tm * HW + p) * CCn + c];
    }
    __syncthreads();
    if (tid >= CP3) return;
    int o = tid;
    u64 acc2[8];
#pragma unroll
    for (int p = 0; p < 8; p++) acc2[p] = 0ull;

    if (o < CPn) {
        for (int k = 0; k < 256; k++) {
            u64 w1d = dup2(d_Wt[k * 168 + o]);
            u64 w2d = dup2(d_Wt[k * 168 + 42 + o]);
            const ulonglong2* rr = (const ulonglong2*)Rs[k];
            const ulonglong2* vv = (const ulonglong2*)Vsm[k];
#pragma unroll
            for (int p = 0; p < 4; p++) {
                ulonglong2 r = rr[p], v = vv[p];
                acc2[2 * p]     = fma2(w1d, r.x, fma2(w2d, v.x, acc2[2 * p]));
                acc2[2 * p + 1] = fma2(w1d, r.y, fma2(w2d, v.y, acc2[2 * p + 1]));
            }
        }
    } else if (o < 2 * CPn) {
        for (int k = 0; k < 256; k++) {
            float w = d_Wt[k * 168 + 84 + (o - CPn)];
            u64 wd = dup2(w), wnd = dup2(-w);
            const ulonglong2* rr = (const ulonglong2*)Rs[k];
            const ulonglong2* vv = (const ulonglong2*)Vsm[k];
#pragma unroll
            for (int p = 0; p < 4; p++) {
                ulonglong2 r = rr[p], v = vv[p];
                acc2[2 * p]     = fma2(wd, r.x, fma2(wnd, v.x, acc2[2 * p]));
                acc2[2 * p + 1] = fma2(wd, r.y, fma2(wnd, v.y, acc2[2 * p + 1]));
            }
        }
    } else {
        for (int k = 0; k < 256; k++) {
            u64 wd = dup2(d_Wt[k * 168 + 126 + (o - 2 * CPn)]);
            const ulonglong2* rr = (const ulonglong2*)Rs[k];
            const ulonglong2* vv = (const ulonglong2*)Vsm[k];
#pragma unroll
            for (int p = 0; p < 4; p++) {
                ulonglong2 r = rr[p], v = vv[p];
                acc2[2 * p]     = fma2(wd, mul2(r.x, v.x), acc2[2 * p]);
                acc2[2 * p + 1] = fma2(wd, mul2(r.y, v.y), acc2[2 * p + 1]);
            }
        }
    }
    float outv[16];
#pragma unroll
    for (int p = 0; p < 8; p++) unpack2(acc2[p], outv[2 * p], outv[2 * p + 1]);
#pragma unroll
    for (int l = 0; l < 16; l++)
        d_Craw[(size_t)o * NLOC + loc0 + l] = outv[l];
}

__global__ void __launch_bounds__(256) k_stats_c()
{
    int ch = blockIdx.x;
    int tid = threadIdx.x;
    const float* p = d_Craw + (size_t)ch * NLOC;
    double s = 0.0, s2 = 0.0;
    for (int i = tid; i < NLOC; i += 256) {
        double v = (double)p[i];
        s += v; s2 += v * v;
    }
    __shared__ double sh[16];
#pragma unroll
    for (int off = 16; off; off >>= 1) {
        s  += __shfl_xor_sync(0xffffffffu, s,  off);
        s2 += __shfl_xor_sync(0xffffffffu, s2, off);
    }
    if ((tid & 31) == 0) { sh[tid >> 5] = s; sh[8 + (tid >> 5)] = s2; }
    __syncthreads();
    if (tid == 0) {
        double S = 0.0, S2 = 0.0;
        for (int i = 0; i < 8; i++) { S += sh[i]; S2 += sh[8 + i]; }
        double n = (double)NLOC;
        double mm = S / n;
        double var = S2 / n - mm * mm;
        d_cmean[ch] = (float)mm;
        d_crstd[ch] = (float)rsqrt(var + 1e-5);
    }
}

__global__ void __launch_bounds__(256) k_stats_z()
{
    int ch = blockIdx.x;
    int tid = threadIdx.x;
    double s = 0.0, s2 = 0.0;
    for (int b = 0; b < Bn; b++) {
        const float* p = d_Z + (size_t)b * Cin * THW + (size_t)ch * THW;
        for (int i = tid; i < THW; i += 256) {
            double v = (double)p[i];
            s += v; s2 += v * v;
        }
    }
    __shared__ double sh[16];
#pragma unroll
    for (int off = 16; off; off >>= 1) {
        s  += __shfl_xor_sync(0xffffffffu, s,  off);
        s2 += __shfl_xor_sync(0xffffffffu, s2, off);
    }
    if ((tid & 31) == 0) { sh[tid >> 5] = s; sh[8 + (tid >> 5)] = s2; }
    __syncthreads();
    if (tid == 0) {
        double S = 0.0, S2 = 0.0;
        for (int i = 0; i < 8; i++) { S += sh[i]; S2 += sh[8 + i]; }
        double n = (double)Bn * (double)THW;
        double mm = S / n;
        double var = S2 / n - mm * mm;
        d_zmean[ch] = (float)mm;
        d_zrstd[ch] = (float)rsqrt(var + 1e-5);
    }
}

__global__ void __launch_bounds__(256) k_rmean()
{
    __shared__ float t[32][33];
    int b = blockIdx.z;
    int n0 = blockIdx.x * 32, c0 = blockIdx.y * 32;
    int tx = threadIdx.x & 31, ty = threadIdx.x >> 5;
#pragma unroll
    for (int i = 0; i < 4; i++) {
        int n = n0 + ty + i * 8;
        float acc = 0.f;
        if (n < THW) {
            int tt = n / HW, p = n % HW;
            const float* base = d_R + ((size_t)(b * 4 + tt) * THW + p) * CCn + c0 + tx;
            acc = base[0] +
                  base[(size_t)1 * HW * CCn] +
                  base[(size_t)2 * HW * CCn] +
                  base[(size_t)3 * HW * CCn];
        }
        t[ty + i * 8][tx] = acc * 0.25f;
    }
    __syncthreads();
#pragma unroll
    for (int i = 0; i < 4; i++) {
        int n = n0 + tx;
        int c = c0 + ty + i * 8;
        if (n < THW) {
            float v = t[tx][ty + i * 8];
            __nv_bfloat16 hh, ll; bfsplit(v, hh, ll);
            size_t off = ((size_t)b * 1024 + c) * NPAD + n;
            d_Yh[off] = hh; d_Yl[off] = ll;
        }
    }
}

__global__ void __launch_bounds__(256) k_ybuild(const float* __restrict__ gc, const float* __restrict__ bc,
                                                const float* __restrict__ gs, const float* __restrict__ bsv,
                                                const float* __restrict__ gm, const float* __restrict__ bmv)
{
    size_t idx = (size_t)blockIdx.x * 256 + threadIdx.x;
    if (idx >= (size_t)Bn * 760 * THW) return;
    int n = (int)(idx % THW);
    int rest = (int)(idx / THW);
    int ch = 256 + rest % 760;
    int b = rest / 760;
    int t = n / HW, p = n % HW;
    float val;
    if (ch < 2 * CCn) {
        val = d_qmv[((size_t)b * 768 + 512 + (ch - CCn)) * THW + n];
    } else {
        int j = ch - 512;
        int c = j >> 2, tm = j & 3;
        size_t loc = (size_t)(b * 16 + tm * 4 + t) * HW + p;
        float raw = d_Craw[(size_t)c * NLOC + loc];
        float g, bb;
        if      (c < CPn)     { g = gc[c];           bb = bc[c]; }
        else if (c < 2 * CPn) { g = gs[c - CPn];     bb = bsv[c - CPn]; }
        else                  { g = gm[c - 2 * CPn]; bb = bmv[c - 2 * CPn]; }
        val = fmaxf((raw - d_cmean[c]) * d_crstd[c] * g + bb, 0.f);
    }
    __nv_bfloat16 hh, ll; bfsplit(val, hh, ll);
    size_t off = ((size_t)b * 1024 + ch) * NPAD + n;
    d_Yh[off] = hh; d_Yl[off] = ll;
}

__global__ void __launch_bounds__(256) k_finalize(const float* __restrict__ g,
                                                  const float* __restrict__ bv,
                                                  float* __restrict__ out)
{
    size_t idx = (size_t)blockIdx.x * 256 + threadIdx.x;
    if (idx >= (size_t)Bn * Cin * THW) return;
    int o = (int)((idx / THW) % Cin);
    float z = (d_Z[idx] - d_zmean[o]) * d_zrstd[o] * g[o] + bv[o];
    out[idx] = fmaxf(d_xp[idx] + z, 0.f);
}

extern "C" void kernel_launch(void* const* d_in, const int* in_sizes, int n_in,
                              void* d_out, int out_size)
{
    const float* x     = (const float*)d_in[0];
    const float* Wq    = (const float*)d_in[1];
    const float* Wm    = (const float*)d_in[2];
    const float* Wv    = (const float*)d_in[3];
    const float* Wcat  = (const float*)d_in[4];
    const float* Wsub  = (const float*)d_in[5];
    const float* Wmul  = (const float*)d_in[6];
    const float* g_cat = (const float*)d_in[7];
    const float* b_cat = (const float*)d_in[8];
    const float* g_sub = (const float*)d_in[9];
    const float* b_sub = (const float*)d_in[10];
    const float* g_mul = (const float*)d_in[11];
    const float* b_mul = (const float*)d_in[12];
    const float* Wagg  = (const float*)d_in[13];
    const float* g_agg = (const float*)d_in[14];
    const float* b_agg = (const float*)d_in[15];
    float* out = (float*)d_out;

    cudaFuncSetAttribute(k_attn, cudaFuncAttributeMaxDynamicSharedMemorySize, AT_SMEM_BYTES);
    cudaFuncSetAttribute(k_gemm_qmv, cudaFuncAttributeMaxDynamicSharedMemorySize, GEMM_SMEM);
    cudaFuncSetAttribute(k_gemm_agg, cudaFuncAttributeMaxDynamicSharedMemorySize, GEMM_SMEM);

    k_pool<<<(Bn * Cin * Tn * HW + 255) / 256, 256>>>(x);
    k_wconv_qmv<<<(3 * 256 * 512 + 255) / 256, 256>>>(Wq, Wm, Wv);
    k_wconv_agg<<<(512 * 1016 + 255) / 256, 256>>>(Wagg);
    k_gemm_qmv<<<dim3((THW + 127) / 128, 2, Bn * 3), 256, GEMM_SMEM>>>();
    k_qvt<<<dim3((THW + 31) / 32, CCn / 32, Bn * 3), 256>>>();
    k_attn<<<dim3(NQT, Tn, Bn), 256, AT_SMEM_BYTES>>>();
    k_wtprep<<<(256 * 168 + 255) / 256, 256>>>(Wcat, Wsub, Wmul);
    k_compare<<<NLOC / 16, 128>>>();
    k_stats_c<<<CP3, 256>>>();
    k_rmean<<<dim3((THW + 31) / 32, CCn / 32, Bn), 256>>>();
    k_ybuild<<<(int)(((size_t)Bn * 760 * THW + 255) / 256), 256>>>(g_cat, b_cat, g_sub, b_sub, g_mul, b_mul);
    k_gemm_agg<<<dim3((THW + 127) / 128, 4, Bn), 256, GEMM_SMEM>>>();
    k_stats_z<<<Cin, 256>>>();
    k_finalize<<<(Bn * Cin * THW + 255) / 256, 256>>>(g_agg, b_agg, out);
}

// round 17
// speedup vs baseline: 1.5536x; 1.5536x over previous
#include <cuda_runtime.h>
#include <cuda_bf16.h>
#include <math.h>
#include <stdint.h>

#define Bn     4
#define Cin    512
#define Tn     4
#define HW     961
#define THW    3844
#define CCn    256
#define CPn    42
#define CP3    126
#define AGGIN  1016
#define NLOC   61504
#define NQT    61
#define VROW   968
#define NPAD   3848

typedef unsigned long long u64;
typedef unsigned int u32;

// ---------------- f32x2 packed-math helpers ----------------
__device__ __forceinline__ u64 pack2(float lo, float hi) {
    u64 r; asm("mov.b64 %0, {%1,%2};" : "=l"(r) : "f"(lo), "f"(hi)); return r;
}
__device__ __forceinline__ u64 dup2(float v) { return pack2(v, v); }
__device__ __forceinline__ void unpack2(u64 p, float& lo, float& hi) {
    asm("mov.b64 {%0,%1}, %2;" : "=f"(lo), "=f"(hi) : "l"(p));
}
__device__ __forceinline__ u64 fma2(u64 a, u64 b, u64 c) {
    u64 d; asm("fma.rn.f32x2 %0, %1, %2, %3;" : "=l"(d) : "l"(a), "l"(b), "l"(c)); return d;
}
__device__ __forceinline__ u64 mul2(u64 a, u64 b) {
    u64 d; asm("mul.rn.f32x2 %0, %1, %2;" : "=l"(d) : "l"(a), "l"(b)); return d;
}

// ---------------- bf16 mma helpers ----------------
__device__ __forceinline__ u32 pkbf(float lo, float hi) {
    u32 d; asm("cvt.rn.bf16x2.f32 %0, %1, %2;" : "=r"(d) : "f"(hi), "f"(lo)); return d;
}
__device__ __forceinline__ void mma_bf16(float* d, u32 a0, u32 a1, u32 a2, u32 a3,
                                         u32 b0, u32 b1)
{
    asm("mma.sync.aligned.m16n8k16.row.col.f32.bf16.bf16.f32 "
        "{%0,%1,%2,%3},{%4,%5,%6,%7},{%8,%9},{%0,%1,%2,%3};"
        : "+f"(d[0]), "+f"(d[1]), "+f"(d[2]), "+f"(d[3])
        : "r"(a0), "r"(a1), "r"(a2), "r"(a3), "r"(b0), "r"(b1));
}
__device__ __forceinline__ void ldsm4(u32& r0, u32& r1, u32& r2, u32& r3, u32 addr) {
    asm volatile("ldmatrix.sync.aligned.m8n8.x4.shared.b16 {%0,%1,%2,%3}, [%4];"
                 : "=r"(r0), "=r"(r1), "=r"(r2), "=r"(r3) : "r"(addr));
}
__device__ __forceinline__ void ldsm4t(u32& r0, u32& r1, u32& r2, u32& r3, u32 addr) {
    asm volatile("ldmatrix.sync.aligned.m8n8.x4.trans.shared.b16 {%0,%1,%2,%3}, [%4];"
                 : "=r"(r0), "=r"(r1), "=r"(r2), "=r"(r3) : "r"(addr));
}
__device__ __forceinline__ void cpa16(u32 smem_addr, const void* gptr) {
    asm volatile("cp.async.cg.shared.global [%0], [%1], 16;"
                 :: "r"(smem_addr), "l"(gptr));
}
#define CP_COMMIT() asm volatile("cp.async.commit_group;")
#define CP_WAIT(N)  asm volatile("cp.async.wait_group %0;" :: "n"(N))

__device__ __forceinline__ void bfsplit(float v, __nv_bfloat16& h, __nv_bfloat16& l) {
    h = __float2bfloat16(v);
    l = __float2bfloat16(v - __bfloat162float(h));
}

// ---------------- scratch ----------------
__device__ float d_xp [(size_t)Bn*Cin*THW];
__device__ float d_qmv[(size_t)Bn*768*THW];
__device__ float d_Vt [(size_t)Bn*THW*CCn];
__device__ __align__(16) __nv_bfloat16 d_Qb[(size_t)Bn*THW*CCn + 2048*CCn];
__device__ __align__(16) __nv_bfloat16 d_Mb[(size_t)Bn*THW*CCn + 2048*CCn];
__device__ __align__(16) __nv_bfloat16 d_Vb[(size_t)Bn*CCn*4*VROW + 64];
__device__ __align__(16) __nv_bfloat16 d_xph[(size_t)Bn*512*NPAD + 256];
__device__ __align__(16) __nv_bfloat16 d_xpl[(size_t)Bn*512*NPAD + 256];
__device__ __align__(16) __nv_bfloat16 d_Yh [(size_t)Bn*1024*NPAD + 256];
__device__ __align__(16) __nv_bfloat16 d_Yl [(size_t)Bn*1024*NPAD + 256];
__device__ __align__(16) __nv_bfloat16 d_Wqmvh[3*256*512], d_Wqmvl[3*256*512];
__device__ __align__(16) __nv_bfloat16 d_Waggh[512*1024],  d_Waggl[512*1024];
__device__ float d_R  [(size_t)Bn*Tn*THW*CCn];
__device__ float d_Wt [256*168];
__device__ float d_Craw[(size_t)CP3*NLOC];
__device__ float d_Z  [(size_t)Bn*Cin*THW];
__device__ float d_cmean[CP3], d_crstd[CP3];
__device__ float d_zmean[Cin], d_zrstd[Cin];

// ---------------- split-bf16 GEMM (3-term), 128x128 tile, K-slice 32 ----------------
#define GA_BUF 10240
#define GB_BUF 8704
#define OFF_AH 0
#define OFF_AL 20480
#define OFF_BH 40960
#define OFF_BL 58368
#define GEMM_SMEM 75776

__device__ __forceinline__ void gemm_bfs(const __nv_bfloat16* __restrict__ Ahg,
                                         const __nv_bfloat16* __restrict__ Alg,
                                         const __nv_bfloat16* __restrict__ Bhg,
                                         const __nv_bfloat16* __restrict__ Blg,
                                         float* __restrict__ C,
                                         int M, int N, int K,
                                         int lda, int ldb, int ldc)
{
    extern __shared__ __align__(16) char gsm[];
    const int tid = threadIdx.x;
    const int lane = tid & 31, w = tid >> 5;
    const int g = lane >> 2, q4 = lane & 3;
    const int wm = w & 3, wn = w >> 2;
    const int m0 = blockIdx.y * 128, n0 = blockIdx.x * 128;
    const u32 sb = (u32)__cvta_generic_to_shared(gsm);

    float acc[2][8][4];
#pragma unroll
    for (int mi = 0; mi < 2; mi++)
#pragma unroll
        for (int n = 0; n < 8; n++)
#pragma unroll
            for (int i = 0; i < 4; i++) acc[mi][n][i] = 0.f;

    const int rowA = lane & 15;
    const u32 hiA = (lane & 16) ? 16 : 0;
    const u32 bOffLane = (u32)((lane & 15) * 272 + ((lane >> 4) & 1) * 16);

    const int ns = K / 32;

    {
#pragma unroll
        for (int i = 0; i < 2; i++) {
            int idx = tid + i * 256;
            int ar = idx >> 2, ac = idx & 3;
            size_t ga = (size_t)(m0 + ar) * lda + ac * 8;
            u32 da = ar * 80 + ac * 16;
            cpa16(sb + OFF_AH + da, Ahg + ga);
            cpa16(sb + OFF_AL + da, Alg + ga);
            int kr = idx >> 4, nc = idx & 15;
            size_t gb = (size_t)kr * ldb + n0 + nc * 8;
            u32 db = kr * 272 + nc * 16;
            cpa16(sb + OFF_BH + db, Bhg + gb);
            cpa16(sb + OFF_BL + db, Blg + gb);
        }
        CP_COMMIT();
    }

    for (int s = 0; s < ns; s++) {
        if (s + 1 < ns) {
            int k0 = (s + 1) * 32, bi = (s + 1) & 1;
#pragma unroll
            for (int i = 0; i < 2; i++) {
                int idx = tid + i * 256;
                int ar = idx >> 2, ac = idx & 3;
                size_t ga = (size_t)(m0 + ar) * lda + k0 + ac * 8;
                u32 da = bi * GA_BUF + ar * 80 + ac * 16;
                cpa16(sb + OFF_AH + da, Ahg + ga);
                cpa16(sb + OFF_AL + da, Alg + ga);
                int kr = idx >> 4, nc = idx & 15;
                size_t gb = (size_t)(k0 + kr) * ldb + n0 + nc * 8;
                u32 db = bi * GB_BUF + kr * 272 + nc * 16;
                cpa16(sb + OFF_BH + db, Bhg + gb);
                cpa16(sb + OFF_BL + db, Blg + gb);
            }
            CP_COMMIT();
            CP_WAIT(1);
        } else {
            CP_WAIT(0);
        }
        __syncthreads();

        const int bi = s & 1;
        const u32 aAh = sb + OFF_AH + bi * GA_BUF + (wm * 32 + rowA) * 80 + hiA;
        const u32 aAl = sb + OFF_AL + bi * GA_BUF + (wm * 32 + rowA) * 80 + hiA;
        const u32 bBh = sb + OFF_BH + bi * GB_BUF + bOffLane + wn * 128;
        const u32 bBl = sb + OFF_BL + bi * GB_BUF + bOffLane + wn * 128;

#pragma unroll
        for (int kg = 0; kg < 2; kg++) {
            const u32 akg = kg * 32;
            const u32 bkg = kg * 4352;
            u32 ah[2][4], al[2][4];
            ldsm4(ah[0][0], ah[0][1], ah[0][2], ah[0][3], aAh + akg);
            ldsm4(ah[1][0], ah[1][1], ah[1][2], ah[1][3], aAh + akg + 16 * 80);
            ldsm4(al[0][0], al[0][1], al[0][2], al[0][3], aAl + akg);
            ldsm4(al[1][0], al[1][1], al[1][2], al[1][3], aAl + akg + 16 * 80);

#pragma unroll
            for (int nn = 0; nn < 4; nn++) {
                u32 bh0, bh1, bh2, bh3, bl0, bl1, bl2, bl3;
                ldsm4t(bh0, bh1, bh2, bh3, bBh + bkg + nn * 32);
                ldsm4t(bl0, bl1, bl2, bl3, bBl + bkg + nn * 32);
#pragma unroll
                for (int mi = 0; mi < 2; mi++) {
                    mma_bf16(acc[mi][nn * 2],     ah[mi][0], ah[mi][1], ah[mi][2], ah[mi][3], bh0, bh1);
                    mma_bf16(acc[mi][nn * 2],     ah[mi][0], ah[mi][1], ah[mi][2], ah[mi][3], bl0, bl1);
                    mma_bf16(acc[mi][nn * 2],     al[mi][0], al[mi][1], al[mi][2], al[mi][3], bh0, bh1);
                    mma_bf16(acc[mi][nn * 2 + 1], ah[mi][0], ah[mi][1], ah[mi][2], ah[mi][3], bh2, bh3);
                    mma_bf16(acc[mi][nn * 2 + 1], ah[mi][0], ah[mi][1], ah[mi][2], ah[mi][3], bl2, bl3);
                    mma_bf16(acc[mi][nn * 2 + 1], al[mi][0], al[mi][1], al[mi][2], al[mi][3], bh2, bh3);
                }
            }
        }
        __syncthreads();
    }

#pragma unroll
    for (int mi = 0; mi < 2; mi++) {
        int gm0 = m0 + wm * 32 + mi * 16 + g;
#pragma unroll
        for (int n = 0; n < 8; n++) {
            int gn = n0 + wn * 64 + n * 8 + q4 * 2;
            if (gn < N) {
                float2 t0 = make_float2(acc[mi][n][0], acc[mi][n][1]);
                float2 t1 = make_float2(acc[mi][n][2], acc[mi][n][3]);
                *(float2*)&C[(size_t)gm0 * ldc + gn] = t0;
                *(float2*)&C[(size_t)(gm0 + 8) * ldc + gn] = t1;
            }
        }
    }
}

// ---------------- elementwise / prep ----------------
__global__ void __launch_bounds__(256) k_pool(const float* __restrict__ x)
{
    int idx = blockIdx.x * 256 + threadIdx.x;
    if (idx >= Bn * Cin * Tn * HW) return;
    int p = idx % HW; int rest = idx / HW;
    int h = p / 31, w = p % 31;
    const float* src = x + (size_t)rest * 3969 + (2 * h) * 63 + (2 * w);
    float v = src[0];
    v = fmaxf(v, src[1]);   v = fmaxf(v, src[2]);
    v = fmaxf(v, src[63]);  v = fmaxf(v, src[64]);  v = fmaxf(v, src[65]);
    v = fmaxf(v, src[126]); v = fmaxf(v, src[127]); v = fmaxf(v, src[128]);
    d_xp[idx] = v;
    int t = rest & 3;
    size_t bc = (size_t)(rest >> 2);
    size_t off = bc * NPAD + t * HW + p;
    __nv_bfloat16 hh, ll; bfsplit(v, hh, ll);
    d_xph[off] = hh; d_xpl[off] = ll;
}

__global__ void __launch_bounds__(256) k_wconv_qmv(const float* __restrict__ Wq,
                                                   const float* __restrict__ Wm,
                                                   const float* __restrict__ Wv)
{
    int idx = blockIdx.x * 256 + threadIdx.x;
    if (idx >= 3 * 256 * 512) return;
    int s = idx / (256 * 512), r = idx % (256 * 512);
    const float* W = (s == 0) ? Wq : (s == 1) ? Wm : Wv;
    __nv_bfloat16 hh, ll; bfsplit(W[r], hh, ll);
    d_Wqmvh[idx] = hh; d_Wqmvl[idx] = ll;
}
__global__ void __launch_bounds__(256) k_wconv_agg(const float* __restrict__ Wagg)
{
    int idx = blockIdx.x * 256 + threadIdx.x;
    if (idx >= 512 * 1016) return;
    int m = idx / 1016, k = idx % 1016;
    __nv_bfloat16 hh, ll; bfsplit(Wagg[idx], hh, ll);
    d_Waggh[m * 1024 + k] = hh; d_Waggl[m * 1024 + k] = ll;
}

__global__ void __launch_bounds__(256, 2) k_gemm_qmv()
{
    int z = blockIdx.z; int b = z / 3, s = z % 3;
    gemm_bfs(d_Wqmvh + (size_t)s * 256 * 512, d_Wqmvl + (size_t)s * 256 * 512,
             d_xph + (size_t)b * 512 * NPAD, d_xpl + (size_t)b * 512 * NPAD,
             d_qmv + (size_t)b * 768 * THW + (size_t)s * 256 * THW,
             256, THW, 512, 512, NPAD, THW);
}

__global__ void __launch_bounds__(256, 2) k_gemm_agg()
{
    int b = blockIdx.z;
    gemm_bfs(d_Waggh, d_Waggl,
             d_Yh + (size_t)b * 1024 * NPAD, d_Yl + (size_t)b * 1024 * NPAD,
             d_Z + (size_t)b * Cin * THW,
             Cin, THW, 1024, 1024, NPAD, THW);
}

// transpose Q/M -> bf16 [token][c] (Q pre-scaled 1/16); V -> f32 [j][c] + bf16 [c][mfr][j]
__global__ void __launch_bounds__(256) k_qvt()
{
    __shared__ float t[32][33];
    int z = blockIdx.z; int b = z / 3, s = z % 3;
    const float* src = d_qmv + ((size_t)b * 768 + s * 256) * THW;
    int q0 = blockIdx.x * 32, c0 = blockIdx.y * 32;
    int tx = threadIdx.x & 31, ty = threadIdx.x >> 5;
#pragma unroll
    for (int i = 0; i < 4; i++) {
        int c = c0 + ty + i * 8;
        int q = q0 + tx;
        t[ty + i * 8][tx] = (q < THW) ? src[(size_t)c * THW + q] : 0.f;
    }
    __syncthreads();
    if (s == 2) {
        int q = q0 + tx;
        if (q < THW) {
            int mfr = q / HW, j = q - mfr * HW;
#pragma unroll
            for (int i = 0; i < 4; i++) {
                int c = c0 + ty + i * 8;
                d_Vb[((size_t)(b * 256 + c) * 4 + mfr) * VROW + j] =
                    __float2bfloat16(t[ty + i * 8][tx]);
            }
        }
    }
#pragma unroll
    for (int i = 0; i < 4; i++) {
        int q = q0 + ty + i * 8;
        int c = c0 + tx;
        if (q >= THW) continue;
        float v = t[tx][ty + i * 8];
        size_t off = ((size_t)b * THW + q) * CCn + c;
        if      (s == 0) d_Qb[off] = __float2bfloat16(v * 0.0625f);
        else if (s == 1) d_Mb[off] = __float2bfloat16(v);
        else             d_Vt[off] = v;
    }
}

// ---------------- bf16 flash attention (exact round-14 scheduling) ----------------
#define AT_QS  0
#define AT_MS  8448
#define AT_PS  16896
#define AT_VS  19200
#define AT_SFM 28416
#define AT_SFS 28544
#define AT_SMEM_BYTES (28672 * 4)

__global__ void __launch_bounds__(256, 2) k_attn()
{
    extern __shared__ __align__(16) u32 smu[];
    u32* Ps = smu + AT_PS;
    float* SfM = (float*)(smu + AT_SFM);
    float* SfS = (float*)(smu + AT_SFS);

    const int b = blockIdx.z, mfr = blockIdx.y;
    const int q0 = blockIdx.x * 64;
    const int tid = threadIdx.x;
    const int w = tid >> 5, lane = tid & 31;
    const int g = lane >> 2, q4 = lane & 3;
    const int qg = w & 3, jh = w >> 2;
    const int qb = qg * 16;

    const __nv_bfloat16* Qg = d_Qb + ((size_t)b * THW + q0) * CCn;
    const __nv_bfloat16* Mg = d_Mb + ((size_t)b * THW + (size_t)mfr * HW) * CCn;
    const __nv_bfloat16* VgBase = d_Vb + ((size_t)b * CCn * 4 + mfr) * VROW;

    const u32 sbase = (u32)__cvta_generic_to_shared(smu);
    const u32 qsB = sbase + AT_QS * 4;
    const u32 msB = sbase + AT_MS * 4;
    const u32 vsB = sbase + AT_VS * 4;

    {
#pragma unroll
        for (int p = 0; p < 8; p++) {
            int e = tid + p * 256;
            int r = e >> 5, seg = e & 31;
            cpa16(qsB + r * 528 + seg * 16, Qg + (size_t)r * CCn + seg * 8);
        }
        CP_COMMIT();
#pragma unroll
        for (int p = 0; p < 8; p++) {
            int e = tid + p * 256;
            int r = e >> 5, seg = e & 31;
            cpa16(msB + r * 528 + seg * 16, Mg + (size_t)r * CCn + seg * 8);
        }
        CP_COMMIT();
    }

    const int rowA = lane & 15;
    const int hiKA = (lane & 16) ? 4 : 0;
    const int rowB = (lane & 7) + ((lane & 16) ? 8 : 0);
    const int hiKB = (lane & 8) ? 4 : 0;
    const u32 aQ  = sbase + (AT_QS + (qb + rowA) * 132 + hiKA) * 4;
    const u32 aM0 = sbase + (AT_MS + (jh * 32 + rowB) * 132 + hiKB) * 4;
    const u32 aM1 = aM0 + 16 * 132 * 4;
    const u32 aP  = sbase + (AT_PS + (qb + rowA) * 36 + hiKA) * 4;
    u32 aV[4];
#pragma unroll
    for (int pp = 0; pp < 4; pp++)
        aV[pp] = sbase + (AT_VS + (jh * 64 + pp * 16 + rowB) * 36 + hiKB) * 4;

    float o[2][8][4];
#pragma unroll
    for (int v = 0; v < 2; v++)
#pragma unroll
        for (int n = 0; n < 8; n++)
#pragma unroll
            for (int i = 0; i < 4; i++) o[v][n][i] = 0.f;
    float rmax0 = -1e30f, rmax1 = -1e30f, rsum0 = 0.f, rsum1 = 0.f;

    for (int j0 = 0; j0 < HW; j0 += 64) {
        CP_WAIT(0);
        __syncthreads();

        // ---- phase A ----
        float s[4][4];
#pragma unroll
        for (int n = 0; n < 4; n++)
#pragma unroll
            for (int i = 0; i < 4; i++) s[n][i] = 0.f;
#pragma unroll
        for (int ks = 0; ks < 16; ks++) {
            u32 a0, a1, a2, a3, b0, b1, b2, b3, c0, c1, c2, c3;
            ldsm4(a0, a1, a2, a3, aQ + ks * 32);
            ldsm4(b0, b1, b2, b3, aM0 + ks * 32);
            ldsm4(c0, c1, c2, c3, aM1 + ks * 32);
            mma_bf16(s[0], a0, a1, a2, a3, b0, b1);
            mma_bf16(s[1], a0, a1, a2, a3, b2, b3);
            mma_bf16(s[2], a0, a1, a2, a3, c0, c1);
            mma_bf16(s[3], a0, a1, a2, a3, c2, c3);
        }

        // ---- softmax: max ----
        float mx0 = -1e30f, mx1 = -1e30f;
#pragma unroll
        for (int n = 0; n < 4; n++) {
            int cb = j0 + jh * 32 + n * 8 + q4 * 2;
            if (cb     >= HW) { s[n][0] = -1e30f; s[n][2] = -1e30f; }
            if (cb + 1 >= HW) { s[n][1] = -1e30f; s[n][3] = -1e30f; }
            mx0 = fmaxf(mx0, fmaxf(s[n][0], s[n][1]));
            mx1 = fmaxf(mx1, fmaxf(s[n][2], s[n][3]));
        }
        mx0 = fmaxf(mx0, __shfl_xor_sync(0xffffffffu, mx0, 1));
        mx0 = fmaxf(mx0, __shfl_xor_sync(0xffffffffu, mx0, 2));
        mx1 = fmaxf(mx1, __shfl_xor_sync(0xffffffffu, mx1, 1));
        mx1 = fmaxf(mx1, __shfl_xor_sync(0xffffffffu, mx1, 2));
        if (q4 == 0) {
            SfM[jh * 64 + qb + g]     = mx0;
            SfM[jh * 64 + qb + g + 8] = mx1;
        }
        __syncthreads();

        // ---- prefetch next M chunk ----
        {
            const __nv_bfloat16* Mg2 = Mg + (size_t)(j0 + 64) * CCn;
#pragma unroll
            for (int p = 0; p < 8; p++) {
                int e = tid + p * 256;
                int r = e >> 5, seg = e & 31;
                cpa16(msB + r * 528 + seg * 16, Mg2 + (size_t)r * CCn + seg * 8);
            }
            CP_COMMIT();
        }

        // ---- softmax: exp/sum, write P ----
        float nm0 = fmaxf(rmax0, fmaxf(SfM[qb + g],     SfM[64 + qb + g]));
        float nm1 = fmaxf(rmax1, fmaxf(SfM[qb + g + 8], SfM[64 + qb + g + 8]));
        float es0 = __expf(rmax0 - nm0), es1 = __expf(rmax1 - nm1);
        rmax0 = nm0; rmax1 = nm1;
        float sm0 = 0.f, sm1 = 0.f;
#pragma unroll
        for (int n = 0; n < 4; n++) {
            int col = jh * 32 + n * 8 + q4 * 2;
            float p0 = __expf(s[n][0] - nm0), p1 = __expf(s[n][1] - nm0);
            float p2 = __expf(s[n][2] - nm1), p3 = __expf(s[n][3] - nm1);
            sm0 += p0 + p1; sm1 += p2 + p3;
            Ps[(qb + g) * 36 + (col >> 1)]     = pkbf(p0, p1);
            Ps[(qb + g + 8) * 36 + (col >> 1)] = pkbf(p2, p3);
        }
        sm0 += __shfl_xor_sync(0xffffffffu, sm0, 1);
        sm0 += __shfl_xor_sync(0xffffffffu, sm0, 2);
        sm1 += __shfl_xor_sync(0xffffffffu, sm1, 1);
        sm1 += __shfl_xor_sync(0xffffffffu, sm1, 2);
        if (q4 == 0) {
            SfS[jh * 64 + qb + g]     = sm0;
            SfS[jh * 64 + qb + g + 8] = sm1;
        }
        __syncthreads();
        float cs0 = SfS[qb + g]     + SfS[64 + qb + g];
        float cs1 = SfS[qb + g + 8] + SfS[64 + qb + g + 8];
        rsum0 = rsum0 * es0 + cs0;
        rsum1 = rsum1 * es1 + cs1;
#pragma unroll
        for (int v = 0; v < 2; v++)
#pragma unroll
            for (int n = 0; n < 8; n++) {
                o[v][n][0] *= es0; o[v][n][1] *= es0;
                o[v][n][2] *= es1; o[v][n][3] *= es1;
            }

        // ---- issue both V chunk copies ----
#pragma unroll
        for (int v = 0; v < 2; v++) {
#pragma unroll
            for (int p = 0; p < 4; p++) {
                int e = tid + p * 256;
                int cr = e >> 3, seg = e & 7;
                cpa16(vsB + v * 18432 + cr * 144 + seg * 16,
                      VgBase + ((size_t)(v * 128 + cr) * 4) * VROW + j0 + seg * 8);
            }
            CP_COMMIT();
        }

        // ---- phase C0: queue [M, V0, V1] -> wait<=1 gives M+V0 done ----
        CP_WAIT(1);
        __syncthreads();
#pragma unroll
        for (int ks = 0; ks < 4; ks++) {
            u32 pa0, pa1, pa2, pa3;
            ldsm4(pa0, pa1, pa2, pa3, aP + ks * 32);
#pragma unroll
            for (int pp = 0; pp < 4; pp++) {
                u32 vb0, vb1, vb2, vb3;
                ldsm4(vb0, vb1, vb2, vb3, aV[pp] + ks * 32);
                mma_bf16(o[0][pp * 2],     pa0, pa1, pa2, pa3, vb0, vb1);
                mma_bf16(o[0][pp * 2 + 1], pa0, pa1, pa2, pa3, vb2, vb3);
            }
        }
        // ---- phase C1 ----
        CP_WAIT(0);
        __syncthreads();
#pragma unroll
        for (int ks = 0; ks < 4; ks++) {
            u32 pa0, pa1, pa2, pa3;
            ldsm4(pa0, pa1, pa2, pa3, aP + ks * 32);
#pragma unroll
            for (int pp = 0; pp < 4; pp++) {
                u32 vb0, vb1, vb2, vb3;
                ldsm4(vb0, vb1, vb2, vb3, aV[pp] + 18432 + ks * 32);
                mma_bf16(o[1][pp * 2],     pa0, pa1, pa2, pa3, vb0, vb1);
                mma_bf16(o[1][pp * 2 + 1], pa0, pa1, pa2, pa3, vb2, vb3);
            }
        }
        // no end sync: next top CP_WAIT(0)+sync orders Ps/Vs reuse
    }
    CP_WAIT(0);

    float inv0 = 1.f / rsum0, inv1 = 1.f / rsum1;
    int r0 = q0 + qb + g, r1 = r0 + 8;
    float* Rp = d_R + ((size_t)(b * 4 + mfr) * THW) * CCn;
#pragma unroll
    for (int v = 0; v < 2; v++)
#pragma unroll
        for (int n = 0; n < 8; n++) {
            int c = v * 128 + jh * 64 + n * 8 + q4 * 2;
            if (r0 < THW) {
                float2 t0 = make_float2(o[v][n][0] * inv0, o[v][n][1] * inv0);
                *(float2*)&Rp[(size_t)r0 * CCn + c] = t0;
            }
            if (r1 < THW) {
                float2 t1 = make_float2(o[v][n][2] * inv1, o[v][n][3] * inv1);
                *(float2*)&Rp[(size_t)r1 * CCn + c] = t1;
            }
        }
}

__global__ void __launch_bounds__(256) k_wtprep(const float* __restrict__ Wcat,
                                                const float* __restrict__ Wsub,
                                                const float* __restrict__ Wmul)
{
    int idx = blockIdx.x * 256 + threadIdx.x;
    if (idx >= 256 * 168) return;
    int wi = idx % 168, k = idx / 168;
    float v;
    if      (wi < 42)  v = Wcat[wi * 512 + k];
    else if (wi < 84)  v = Wcat[(wi - 42) * 512 + 256 + k];
    else if (wi < 126) v = Wsub[(wi - 84) * 256 + k];
    else               v = Wmul[(wi - 126) * 256 + k];
    d_Wt[idx] = v;
}

// compare: 16 locs/block static smem + LDS.128 row reads
__global__ void __launch_bounds__(128) k_compare()
{
    __shared__ __align__(16) float Rs[256][16];
    __shared__ __align__(16) float Vsm[256][16];
    int loc0 = blockIdx.x * 16;
    int tid = threadIdx.x;
    for (int i = tid; i < 256 * 16; i += 128) {
        int c = i & 255, l = i >> 8;
        int loc = loc0 + l;
        int p = loc % HW; int bs = loc / HW;
        int s = bs & 15, b = bs >> 4;
        int tm = s >> 2, tq = s & 3;
        Rs[c][l]  = d_R [((size_t)((b * 4 + tm) * THW) + tq * HW + p) * CCn + c];
        Vsm[c][l] = d_Vt[((size_t)b * THW + tm * HW + p) * CCn + c];
    }
    __syncthreads();
    if (tid >= CP3) return;
    int o = tid;
    u64 acc2[8];
#pragma unroll
    for (int p = 0; p < 8; p++) acc2[p] = 0ull;

    if (o < CPn) {
        for (int k = 0; k < 256; k++) {
            u64 w1d = dup2(d_Wt[k * 168 + o]);
            u64 w2d = dup2(d_Wt[k * 168 + 42 + o]);
            const ulonglong2* rr = (const ulonglong2*)Rs[k];
            const ulonglong2* vv = (const ulonglong2*)Vsm[k];
#pragma unroll
            for (int p = 0; p < 4; p++) {
                ulonglong2 r = rr[p], v = vv[p];
                acc2[2 * p]     = fma2(w1d, r.x, fma2(w2d, v.x, acc2[2 * p]));
                acc2[2 * p + 1] = fma2(w1d, r.y, fma2(w2d, v.y, acc2[2 * p + 1]));
            }
        }
    } else if (o < 2 * CPn) {
        for (int k = 0; k < 256; k++) {
            float w = d_Wt[k * 168 + 84 + (o - CPn)];
            u64 wd = dup2(w), wnd = dup2(-w);
            const ulonglong2* rr = (const ulonglong2*)Rs[k];
            const ulonglong2* vv = (const ulonglong2*)Vsm[k];
#pragma unroll
            for (int p = 0; p < 4; p++) {
                ulonglong2 r = rr[p], v = vv[p];
                acc2[2 * p]     = fma2(wd, r.x, fma2(wnd, v.x, acc2[2 * p]));
                acc2[2 * p + 1] = fma2(wd, r.y, fma2(wnd, v.y, acc2[2 * p + 1]));
            }
        }
    } else {
        for (int k = 0; k < 256; k++) {
            u64 wd = dup2(d_Wt[k * 168 + 126 + (o - 2 * CPn)]);
            const ulonglong2* rr = (const ulonglong2*)Rs[k];
            const ulonglong2* vv = (const ulonglong2*)Vsm[k];
#pragma unroll
            for (int p = 0; p < 4; p++) {
                ulonglong2 r = rr[p], v = vv[p];
                acc2[2 * p]     = fma2(wd, mul2(r.x, v.x), acc2[2 * p]);
                acc2[2 * p + 1] = fma2(wd, mul2(r.y, v.y), acc2[2 * p + 1]);
            }
        }
    }
    float outv[16];
#pragma unroll
    for (int p = 0; p < 8; p++) unpack2(acc2[p], outv[2 * p], outv[2 * p + 1]);
#pragma unroll
    for (int l = 0; l < 16; l++)
        d_Craw[(size_t)o * NLOC + loc0 + l] = outv[l];
}

__global__ void __launch_bounds__(256) k_stats_c()
{
    int ch = blockIdx.x;
    int tid = threadIdx.x;
    const float* p = d_Craw + (size_t)ch * NLOC;
    double s = 0.0, s2 = 0.0;
    for (int i = tid; i < NLOC; i += 256) {
        double v = (double)p[i];
        s += v; s2 += v * v;
    }
    __shared__ double sh[16];
#pragma unroll
    for (int off = 16; off; off >>= 1) {
        s  += __shfl_xor_sync(0xffffffffu, s,  off);
        s2 += __shfl_xor_sync(0xffffffffu, s2, off);
    }
    if ((tid & 31) == 0) { sh[tid >> 5] = s; sh[8 + (tid >> 5)] = s2; }
    __syncthreads();
    if (tid == 0) {
        double S = 0.0, S2 = 0.0;
        for (int i = 0; i < 8; i++) { S += sh[i]; S2 += sh[8 + i]; }
        double n = (double)NLOC;
        double mm = S / n;
        double var = S2 / n - mm * mm;
        d_cmean[ch] = (float)mm;
        d_crstd[ch] = (float)rsqrt(var + 1e-5);
    }
}

__global__ void __launch_bounds__(256) k_stats_z()
{
    int ch = blockIdx.x;
    int tid = threadIdx.x;
    double s = 0.0, s2 = 0.0;
    for (int b = 0; b < Bn; b++) {
        const float* p = d_Z + (size_t)b * Cin * THW + (size_t)ch * THW;
        for (int i = tid; i < THW; i += 256) {
            double v = (double)p[i];
            s += v; s2 += v * v;
        }
    }
    __shared__ double sh[16];
#pragma unroll
    for (int off = 16; off; off >>= 1) {
        s  += __shfl_xor_sync(0xffffffffu, s,  off);
        s2 += __shfl_xor_sync(0xffffffffu, s2, off);
    }
    if ((tid & 31) == 0) { sh[tid >> 5] = s; sh[8 + (tid >> 5)] = s2; }
    __syncthreads();
    if (tid == 0) {
        double S = 0.0, S2 = 0.0;
        for (int i = 0; i < 8; i++) { S += sh[i]; S2 += sh[8 + i]; }
        double n = (double)Bn * (double)THW;
        double mm = S / n;
        double var = S2 / n - mm * mm;
        d_zmean[ch] = (float)mm;
        d_zrstd[ch] = (float)rsqrt(var + 1e-5);
    }
}

__global__ void __launch_bounds__(256) k_rmean()
{
    __shared__ float t[32][33];
    int b = blockIdx.z;
    int n0 = blockIdx.x * 32, c0 = blockIdx.y * 32;
    int tx = threadIdx.x & 31, ty = threadIdx.x >> 5;
#pragma unroll
    for (int i = 0; i < 4; i++) {
        int n = n0 + ty + i * 8;
        float acc = 0.f;
        if (n < THW) {
            int tt = n / HW, p = n % HW;
            const float* base = d_R + ((size_t)(b * 4 + tt) * THW + p) * CCn + c0 + tx;
            acc = base[0] +
                  base[(size_t)1 * HW * CCn] +
                  base[(size_t)2 * HW * CCn] +
                  base[(size_t)3 * HW * CCn];
        }
        t[ty + i * 8][tx] = acc * 0.25f;
    }
    __syncthreads();
#pragma unroll
    for (int i = 0; i < 4; i++) {
        int n = n0 + tx;
        int c = c0 + ty + i * 8;
        if (n < THW) {
            float v = t[tx][ty + i * 8];
            __nv_bfloat16 hh, ll; bfsplit(v, hh, ll);
            size_t off = ((size_t)b * 1024 + c) * NPAD + n;
            d_Yh[off] = hh; d_Yl[off] = ll;
        }
    }
}

__global__ void __launch_bounds__(256) k_ybuild(const float* __restrict__ gc, const float* __restrict__ bc,
                                                const float* __restrict__ gs, const float* __restrict__ bsv,
                                                const float* __restrict__ gm, const float* __restrict__ bmv)
{
    size_t idx = (size_t)blockIdx.x * 256 + threadIdx.x;
    if (idx >= (size_t)Bn * 760 * THW) return;
    int n = (int)(idx % THW);
    int rest = (int)(idx / THW);
    int ch = 256 + rest % 760;
    int b = rest / 760;
    int t = n / HW, p = n % HW;
    float val;
    if (ch < 2 * CCn) {
        val = d_qmv[((size_t)b * 768 + 512 + (ch - CCn)) * THW + n];
    } else {
        int j = ch - 512;
        int c = j >> 2, tm = j & 3;
        size_t loc = (size_t)(b * 16 + tm * 4 + t) * HW + p;
        float raw = d_Craw[(size_t)c * NLOC + loc];
        float g, bb;
        if      (c < CPn)     { g = gc[c];           bb = bc[c]; }
        else if (c < 2 * CPn) { g = gs[c - CPn];     bb = bsv[c - CPn]; }
        else                  { g = gm[c - 2 * CPn]; bb = bmv[c - 2 * CPn]; }
        val = fmaxf((raw - d_cmean[c]) * d_crstd[c] * g + bb, 0.f);
    }
    __nv_bfloat16 hh, ll; bfsplit(val, hh, ll);
    size_t off = ((size_t)b * 1024 + ch) * NPAD + n;
    d_Yh[off] = hh; d_Yl[off] = ll;
}

__global__ void __launch_bounds__(256) k_finalize(const float* __restrict__ g,
                                                  const float* __restrict__ bv,
                                                  float* __restrict__ out)
{
    size_t idx = (size_t)blockIdx.x * 256 + threadIdx.x;
    if (idx >= (size_t)Bn * Cin * THW) return;
    int o = (int)((idx / THW) % Cin);
    float z = (d_Z[idx] - d_zmean[o]) * d_zrstd[o] * g[o] + bv[o];
    out[idx] = fmaxf(d_xp[idx] + z, 0.f);
}

extern "C" void kernel_launch(void* const* d_in, const int* in_sizes, int n_in,
                              void* d_out, int out_size)
{
    const float* x     = (const float*)d_in[0];
    const float* Wq    = (const float*)d_in[1];
    const float* Wm    = (const float*)d_in[2];
    const float* Wv    = (const float*)d_in[3];
    const float* Wcat  = (const float*)d_in[4];
    const float* Wsub  = (const float*)d_in[5];
    const float* Wmul  = (const float*)d_in[6];
    const float* g_cat = (const float*)d_in[7];
    const float* b_cat = (const float*)d_in[8];
    const float* g_sub = (const float*)d_in[9];
    const float* b_sub = (const float*)d_in[10];
    const float* g_mul = (const float*)d_in[11];
    const float* b_mul = (const float*)d_in[12];
    const float* Wagg  = (const float*)d_in[13];
    const float* g_agg = (const float*)d_in[14];
    const float* b_agg = (const float*)d_in[15];
    float* out = (float*)d_out;

    cudaFuncSetAttribute(k_attn, cudaFuncAttributeMaxDynamicSharedMemorySize, AT_SMEM_BYTES);
    cudaFuncSetAttribute(k_gemm_qmv, cudaFuncAttributeMaxDynamicSharedMemorySize, GEMM_SMEM);
    cudaFuncSetAttribute(k_gemm_agg, cudaFuncAttributeMaxDynamicSharedMemorySize, GEMM_SMEM);

    k_pool<<<(Bn * Cin * Tn * HW + 255) / 256, 256>>>(x);
    k_wconv_qmv<<<(3 * 256 * 512 + 255) / 256, 256>>>(Wq, Wm, Wv);
    k_wconv_agg<<<(512 * 1016 + 255) / 256, 256>>>(Wagg);
    k_gemm_qmv<<<dim3((THW + 127) / 128, 2, Bn * 3), 256, GEMM_SMEM>>>();
    k_qvt<<<dim3((THW + 31) / 32, CCn / 32, Bn * 3), 256>>>();
    k_attn<<<dim3(NQT, Tn, Bn), 256, AT_SMEM_BYTES>>>();
    k_wtprep<<<(256 * 168 + 255) / 256, 256>>>(Wcat, Wsub, Wmul);
    k_compare<<<NLOC / 16, 128>>>();
    k_stats_c<<<CP3, 256>>>();
    k_rmean<<<dim3((THW + 31) / 32, CCn / 32, Bn), 256>>>();
    k_ybuild<<<(int)(((size_t)Bn * 760 * THW + 255) / 256), 256>>>(g_cat, b_cat, g_sub, b_sub, g_mul, b_mul);
    k_gemm_agg<<<dim3((THW + 127) / 128, 4, Bn), 256, GEMM_SMEM>>>();
    k_stats_z<<<Cin, 256>>>();
    k_finalize<<<(Bn * Cin * THW + 255) / 256, 256>>>(g_agg, b_agg, out);
}